// round 12
// baseline (speedup 1.0000x reference)
#include <cuda_runtime.h>
#include <cstdint>

// Problem constants (fixed shapes for this problem instance)
#define B_ 32
#define T_ 10
#define P_ 25
#define H_ 100
#define W_ 100

#define NPTS      (B_ * T_ * P_)             // 8000 points
#define OUT_ELEMS (B_ * T_ * H_ * W_ * P_)   // 80,000,000 floats = 320 MB
#define OUT_VEC4  (OUT_ELEMS / 4)            // 20,000,000 float4s

#define FILL_BLOCKS  1184                    // 148 SMs * 8 (single wave)
#define FILL_THREADS 1024

// Completion counter for the last-block scatter. Static-zero initialized;
// the last block resets it to 0 each run -> deterministic across graph replays.
__device__ unsigned int g_done_counter = 0;

// ---------------------------------------------------------------------------
// Fused kernel:
//   1) block 0 prefetches the (tiny) inputs into L2
//   2) all blocks: grid-stride zero-fill, 8-way unrolled streaming STG.128
//      (measured ~7 TB/s)
//   3) fence + atomic ticket; the LAST block to finish performs the 8000-point
//      scatter (inputs now L2-hot), then resets the counter.
// Scatter correctness: every point owns a distinct innermost-p output slot ->
// no collisions -> plain store == reference's scatter-max. The fence/ticket
// pairing guarantees all fill zeros are globally visible before any 1.0f is
// written, so no zero can clobber a one. Truncating (int) cast == astype(int32).
// ---------------------------------------------------------------------------
__global__ void __launch_bounds__(FILL_THREADS) fused_fill_scatter_kernel(
        const float* __restrict__ x,
        const float* __restrict__ resolution,
        const float* __restrict__ origin,
        float* __restrict__ outf) {
    // --- 1) prefetch inputs into L2 (block 0 only; ~540 cache lines) ---
    if (blockIdx.x == 0) {
        int t = threadIdx.x;
        if (t < 500) {          // x: 16000 floats = 64000 B = 500 lines
            asm volatile("prefetch.global.L2 [%0];" :: "l"((const char*)x + (size_t)t * 128));
        } else if (t < 520) {   // resolution: 640 floats = 2560 B = 20 lines
            asm volatile("prefetch.global.L2 [%0];" :: "l"((const char*)resolution + (size_t)(t - 500) * 128));
        } else if (t < 540) {   // origin: 640 floats = 2560 B = 20 lines
            asm volatile("prefetch.global.L2 [%0];" :: "l"((const char*)origin + (size_t)(t - 520) * 128));
        }
    }

    // --- 2) zero-fill 320 MB ---
    float4* __restrict__ out = (float4*)outf;
    const float4 z = make_float4(0.f, 0.f, 0.f, 0.f);
    const size_t stride = (size_t)FILL_BLOCKS * FILL_THREADS;      // 1,212,416
    size_t i = (size_t)blockIdx.x * FILL_THREADS + threadIdx.x;

    const size_t end8 = (size_t)OUT_VEC4 > 7 * stride ? (size_t)OUT_VEC4 - 7 * stride : 0;
    for (; i < end8; i += 8 * stride) {
        __stcs(&out[i],              z);
        __stcs(&out[i +     stride], z);
        __stcs(&out[i + 2 * stride], z);
        __stcs(&out[i + 3 * stride], z);
        __stcs(&out[i + 4 * stride], z);
        __stcs(&out[i + 5 * stride], z);
        __stcs(&out[i + 6 * stride], z);
        __stcs(&out[i + 7 * stride], z);
    }
    for (; i < (size_t)OUT_VEC4; i += stride) {
        __stcs(&out[i], z);
    }

    // --- 3) last-block scatter ---
    __threadfence();            // publish this block's zeros
    __syncthreads();

    __shared__ unsigned int ticket;
    if (threadIdx.x == 0) {
        ticket = atomicAdd(&g_done_counter, 1u);
    }
    __syncthreads();

    if (ticket == (unsigned)(FILL_BLOCKS - 1)) {
        __threadfence();        // acquire: all other blocks' zeros now visible

        for (int pt = threadIdx.x; pt < NPTS; pt += FILL_THREADS) {
            int p  = pt % P_;
            int bt = pt / P_;   // b*T + t

            // x layout: [B, T, 2P]; point p is (x, y) at (2p, 2p+1)
            const float2 pxy = *(const float2*)(x + (size_t)bt * (2 * P_) + 2 * p);
            // resolution/origin layout: [B, T, 2]
            const float2 res = *(const float2*)(resolution + 2 * bt);
            const float2 org = *(const float2*)(origin + 2 * bt);

            int row = (int)(pxy.y / res.x + org.x);  // truncating cast == astype(int32)
            int col = (int)(pxy.x / res.y + org.y);

            if (row >= 0 && row < H_ && col >= 0 && col < W_) {
                size_t idx = ((((size_t)bt * H_ + row) * W_) + col) * P_ + p;
                outf[idx] = 1.0f;
            }
        }

        // Reset for the next graph replay (no adds can still be pending:
        // we only get here after all FILL_BLOCKS increments).
        if (threadIdx.x == 0) {
            g_done_counter = 0;
        }
    }
}

extern "C" void kernel_launch(void* const* d_in, const int* in_sizes, int n_in,
                              void* d_out, int out_size) {
    const float* x          = (const float*)d_in[0];
    const float* resolution = (const float*)d_in[1];
    const float* origin     = (const float*)d_in[2];
    float* out = (float*)d_out;

    fused_fill_scatter_kernel<<<FILL_BLOCKS, FILL_THREADS>>>(x, resolution, origin, out);
}

// round 13
// speedup vs baseline: 1.5233x; 1.5233x over previous
#include <cuda_runtime.h>
#include <cstdint>

// Problem constants (fixed shapes for this problem instance)
#define B_ 32
#define T_ 10
#define P_ 25
#define H_ 100
#define W_ 100

#define OUT_ELEMS (B_ * T_ * H_ * W_ * P_)   // 80,000,000 floats = 320 MB
#define OUT_VEC4  (OUT_ELEMS / 4)            // 20,000,000 float4s

#define FILL_BLOCKS  1184                    // 148 SMs * 8 (4 waves of 2 CTAs/SM)
#define FILL_THREADS 1024

// ---------------------------------------------------------------------------
// Kernel 1: zero-fill with grid-stride, 8-way unrolled streaming STG.128.
// Best-measured config: ~45.3us = ~7.1 TB/s (88% of HBM spec).
// __stcs: evict-first, don't hold 320MB of zeros in L2.
// ---------------------------------------------------------------------------
__global__ void __launch_bounds__(FILL_THREADS) zero_fill_kernel(float4* __restrict__ out) {
    const float4 z = make_float4(0.f, 0.f, 0.f, 0.f);
    const size_t stride = (size_t)FILL_BLOCKS * FILL_THREADS;      // 1,212,416
    size_t i = (size_t)blockIdx.x * FILL_THREADS + threadIdx.x;

    const size_t end8 = (size_t)OUT_VEC4 > 7 * stride ? (size_t)OUT_VEC4 - 7 * stride : 0;
    for (; i < end8; i += 8 * stride) {
        __stcs(&out[i],              z);
        __stcs(&out[i +     stride], z);
        __stcs(&out[i + 2 * stride], z);
        __stcs(&out[i + 3 * stride], z);
        __stcs(&out[i + 4 * stride], z);
        __stcs(&out[i + 5 * stride], z);
        __stcs(&out[i + 6 * stride], z);
        __stcs(&out[i + 7 * stride], z);
    }
    for (; i < (size_t)OUT_VEC4; i += stride) {
        __stcs(&out[i], z);
    }
}

// ---------------------------------------------------------------------------
// Kernel 2: scatter 1.0f per in-bounds point. One thread per (b, t, p).
// Each point owns a distinct innermost-p slot -> no collisions -> plain
// store == the reference's scatter-max. Truncating (int) cast matches
// jnp astype(int32). 125 blocks x 64 threads = best measured (4.06us).
// ---------------------------------------------------------------------------
__global__ void __launch_bounds__(64) scatter_points_kernel(
        const float* __restrict__ x,
        const float* __restrict__ resolution,
        const float* __restrict__ origin,
        float* __restrict__ out) {
    int i = blockIdx.x * blockDim.x + threadIdx.x;  // 0 .. B*T*P-1
    if (i >= B_ * T_ * P_) return;

    int p  = i % P_;
    int bt = i / P_;          // b*T + t

    // x layout: [B, T, 2P]; point p is (x, y) at (2p, 2p+1)
    const float2 pxy = *(const float2*)(x + (size_t)bt * (2 * P_) + 2 * p);

    // resolution/origin layout: [B, T, 2]
    const float2 res = *(const float2*)(resolution + 2 * bt);
    const float2 org = *(const float2*)(origin + 2 * bt);

    int row = (int)(pxy.y / res.x + org.x);  // truncating cast == astype(int32)
    int col = (int)(pxy.x / res.y + org.y);

    if (row >= 0 && row < H_ && col >= 0 && col < W_) {
        size_t idx = ((((size_t)bt * H_ + row) * W_) + col) * P_ + p;
        out[idx] = 1.0f;
    }
}

extern "C" void kernel_launch(void* const* d_in, const int* in_sizes, int n_in,
                              void* d_out, int out_size) {
    const float* x          = (const float*)d_in[0];
    const float* resolution = (const float*)d_in[1];
    const float* origin     = (const float*)d_in[2];
    float* out = (float*)d_out;

    // 1) zero-fill 320MB of output
    zero_fill_kernel<<<FILL_BLOCKS, FILL_THREADS>>>((float4*)out);

    // 2) scatter 8000 points (same stream -> ordered after the fill)
    {
        const int total   = B_ * T_ * P_;  // 8000
        const int threads = 64;
        const int blocks  = (total + threads - 1) / threads;  // 125
        scatter_points_kernel<<<blocks, threads>>>(x, resolution, origin, out);
    }
}

// round 14
// speedup vs baseline: 1.5478x; 1.0160x over previous
#include <cuda_runtime.h>
#include <cstdint>

// Problem constants (fixed shapes for this problem instance)
#define B_ 32
#define T_ 10
#define P_ 25
#define H_ 100
#define W_ 100

#define OUT_ELEMS (B_ * T_ * H_ * W_ * P_)   // 80,000,000 floats = 320 MB
#define OUT_VEC8  (OUT_ELEMS / 8)            // 10,000,000 32B granules

#define FILL_BLOCKS  1184                    // 148 SMs * 8
#define FILL_THREADS 1024

// 256-bit streaming store (sm_100+: st.global.v8.f32). Writes 32B of zeros.
__device__ __forceinline__ void st_zero_256(float* p) {
    asm volatile(
        "st.global.cs.v8.f32 [%0], {%1, %1, %1, %1, %1, %1, %1, %1};"
        :: "l"(p), "f"(0.0f) : "memory");
}

// ---------------------------------------------------------------------------
// Kernel 1: zero-fill with grid-stride, 8-way unrolled 256-bit streaming
// stores (STG.E.256, sm_100+). Halves the store-instruction count vs
// STG.128 at identical coalescing (consecutive threads -> consecutive 32B).
// .cs: evict-first, don't hold 320MB of zeros in L2.
// ---------------------------------------------------------------------------
__global__ void __launch_bounds__(FILL_THREADS) zero_fill_kernel(float* __restrict__ outf) {
    const size_t stride = (size_t)FILL_BLOCKS * FILL_THREADS;      // 1,212,416 (in vec8 units)
    size_t i = (size_t)blockIdx.x * FILL_THREADS + threadIdx.x;

    const size_t end8 = (size_t)OUT_VEC8 > 7 * stride ? (size_t)OUT_VEC8 - 7 * stride : 0;
    for (; i < end8; i += 8 * stride) {
        st_zero_256(outf + 8 * i);
        st_zero_256(outf + 8 * (i +     stride));
        st_zero_256(outf + 8 * (i + 2 * stride));
        st_zero_256(outf + 8 * (i + 3 * stride));
        st_zero_256(outf + 8 * (i + 4 * stride));
        st_zero_256(outf + 8 * (i + 5 * stride));
        st_zero_256(outf + 8 * (i + 6 * stride));
        st_zero_256(outf + 8 * (i + 7 * stride));
    }
    for (; i < (size_t)OUT_VEC8; i += stride) {
        st_zero_256(outf + 8 * i);
    }
}

// ---------------------------------------------------------------------------
// Kernel 2: scatter 1.0f per in-bounds point, PDL-launched (hides launch
// latency under the fill; ordering of the store is guaranteed by
// cudaGridDependencySynchronize). One thread per (b, t, p); each point owns
// a distinct innermost-p slot -> no collisions -> plain store == the
// reference's scatter-max. Truncating (int) cast == astype(int32).
// ---------------------------------------------------------------------------
__global__ void __launch_bounds__(64) scatter_points_kernel(
        const float* __restrict__ x,
        const float* __restrict__ resolution,
        const float* __restrict__ origin,
        float* __restrict__ out) {
    int i = blockIdx.x * blockDim.x + threadIdx.x;  // 0 .. B*T*P-1

    size_t idx = 0;
    bool write = false;

    if (i < B_ * T_ * P_) {
        int p  = i % P_;
        int bt = i / P_;          // b*T + t

        // x layout: [B, T, 2P]; point p is (x, y) at (2p, 2p+1)
        const float2 pxy = *(const float2*)(x + (size_t)bt * (2 * P_) + 2 * p);
        // resolution/origin layout: [B, T, 2]
        const float2 res = *(const float2*)(resolution + 2 * bt);
        const float2 org = *(const float2*)(origin + 2 * bt);

        int row = (int)(pxy.y / res.x + org.x);  // truncating cast == astype(int32)
        int col = (int)(pxy.x / res.y + org.y);

        if (row >= 0 && row < H_ && col >= 0 && col < W_) {
            idx = ((((size_t)bt * H_ + row) * W_) + col) * P_ + p;
            write = true;
        }
    }

    // Wait until the fill's stores are visible, then commit.
    cudaGridDependencySynchronize();

    if (write) {
        out[idx] = 1.0f;
    }
}

extern "C" void kernel_launch(void* const* d_in, const int* in_sizes, int n_in,
                              void* d_out, int out_size) {
    const float* x          = (const float*)d_in[0];
    const float* resolution = (const float*)d_in[1];
    const float* origin     = (const float*)d_in[2];
    float* out = (float*)d_out;

    // 1) zero-fill 320MB of output with 256-bit streaming stores
    zero_fill_kernel<<<FILL_BLOCKS, FILL_THREADS>>>(out);

    // 2) scatter 8000 points, PDL launch (launch latency hidden under fill)
    {
        const int total   = B_ * T_ * P_;  // 8000
        const int threads = 64;
        const int blocks  = (total + threads - 1) / threads;  // 125

        cudaLaunchConfig_t cfg = {};
        cfg.gridDim  = dim3(blocks);
        cfg.blockDim = dim3(threads);
        cfg.dynamicSmemBytes = 0;
        cfg.stream = 0;

        cudaLaunchAttribute attrs[1];
        attrs[0].id = cudaLaunchAttributeProgrammaticStreamSerialization;
        attrs[0].val.programmaticStreamSerializationAllowed = 1;
        cfg.attrs = attrs;
        cfg.numAttrs = 1;

        cudaLaunchKernelEx(&cfg, scatter_points_kernel, x, resolution, origin, out);
    }
}